// round 15
// baseline (speedup 1.0000x reference)
#include <cuda_runtime.h>
#include <cstdint>

#define TT 4096
#define BB 32
#define HH 256
#define EPS 1e-12f

typedef unsigned long long u64;

__device__ float g_bsn[HH];
__device__ float g_inv_sig_ih;
__device__ float g_inv_sig_hh;

__device__ __forceinline__ void ffma2(u64& d, u64 a, u64 b) {
    asm("fma.rn.f32x2 %0, %1, %2, %0;" : "+l"(d) : "l"(a), "l"(b));
}
__device__ __forceinline__ u64 pk2(float x, float y) {
    u64 r; asm("mov.b64 %0, {%1, %2};" : "=l"(r) : "f"(x), "f"(y)); return r;
}
__device__ __forceinline__ float2 upk2(u64 v) {
    float lo, hi; asm("mov.b64 {%0, %1}, %2;" : "=f"(lo), "=f"(hi) : "l"(v));
    return make_float2(lo, hi);
}
__device__ __forceinline__ uint32_t smem_u32(const void* p) {
    uint32_t a;
    asm("{ .reg .u64 t; cvta.to.shared.u64 t, %1; cvt.u32.u64 %0, t; }" : "=r"(a) : "l"(p));
    return a;
}
__device__ __forceinline__ uint32_t mapa_u32(uint32_t a, uint32_t r) {
    uint32_t d; asm("mapa.shared::cluster.u32 %0, %1, %2;" : "=r"(d) : "r"(a), "r"(r));
    return d;
}
__device__ __forceinline__ uint32_t ctarank() {
    uint32_t r; asm("mov.u32 %0, %%cluster_ctarank;" : "=r"(r)); return r;
}
__device__ __forceinline__ void mbar_init(uint32_t mb, uint32_t cnt) {
    asm volatile("mbarrier.init.shared.b64 [%0], %1;" :: "r"(mb), "r"(cnt) : "memory");
}
__device__ __forceinline__ void mbar_arrive_expect_tx(uint32_t mb, uint32_t tx) {
    asm volatile("mbarrier.arrive.expect_tx.shared.b64 _, [%0], %1;" :: "r"(mb), "r"(tx) : "memory");
}
__device__ __forceinline__ void st_async_b32(uint32_t raddr, uint32_t v, uint32_t rmbar) {
    asm volatile("st.async.shared::cluster.mbarrier::complete_tx::bytes.b32 [%0], %1, [%2];"
                 :: "r"(raddr), "r"(v), "r"(rmbar) : "memory");
}
__device__ __forceinline__ void waitpar(uint32_t mb, uint32_t par) {
    uint32_t done;
    do {
        asm volatile(
            "{\n\t"
            ".reg .pred p;\n\t"
            "mbarrier.try_wait.parity.acquire.cta.shared::cta.b64 p, [%1], %2, 0x989680;\n\t"
            "selp.b32 %0, 1, 0, p;\n\t"
            "}" : "=r"(done) : "r"(mb), "r"(par) : "memory");
    } while (!done);
}
__device__ __forceinline__ float tanh_fast(float x) {
    float r; asm("tanh.approx.f32 %0, %1;" : "=f"(r) : "f"(x)); return r;
}
__device__ __forceinline__ void cluster_sync() {
    asm volatile("barrier.cluster.arrive.aligned;" ::: "memory");
    asm volatile("barrier.cluster.wait.aligned;" ::: "memory");
}

// ---------------- prep (unchanged, proven) ----------------
__device__ float bsum(float v) {
    __shared__ float sred[8];
    int lane = threadIdx.x & 31, w = threadIdx.x >> 5;
    #pragma unroll
    for (int o = 16; o; o >>= 1) v += __shfl_xor_sync(0xffffffffu, v, o);
    if (lane == 0) sred[w] = v;
    __syncthreads();
    float r = sred[0];
    #pragma unroll
    for (int i = 1; i < 8; i++) r += sred[i];
    __syncthreads();
    return r;
}

__device__ float sigma256(const float* __restrict__ w, const float* __restrict__ u0) {
    __shared__ float u[256], v[256];
    int tid = threadIdx.x;
    float u0t = u0[tid];
    float nu = sqrtf(bsum(u0t * u0t));
    u[tid] = u0t / (nu + EPS);
    __syncthreads();
    float a0 = 0.f, a1 = 0.f, a2 = 0.f, a3 = 0.f;
    #pragma unroll 4
    for (int j = 0; j < 256; j += 4) {
        a0 += w[(j + 0) * 256 + tid] * u[j + 0];
        a1 += w[(j + 1) * 256 + tid] * u[j + 1];
        a2 += w[(j + 2) * 256 + tid] * u[j + 2];
        a3 += w[(j + 3) * 256 + tid] * u[j + 3];
    }
    float acc = (a0 + a1) + (a2 + a3);
    float nv = sqrtf(bsum(acc * acc));
    v[tid] = acc / (nv + EPS);
    __syncthreads();
    float c0 = 0.f, c1 = 0.f, c2 = 0.f, c3 = 0.f;
    const float4* wr = (const float4*)(w + (size_t)tid * 256);
    #pragma unroll 4
    for (int i = 0; i < 64; i += 4) {
        float4 w0 = wr[i], w1 = wr[i+1], w2 = wr[i+2], w3 = wr[i+3];
        c0 += w0.x*v[4*i+0] + w0.y*v[4*i+1] + w0.z*v[4*i+2] + w0.w*v[4*i+3];
        c1 += w1.x*v[4*i+4] + w1.y*v[4*i+5] + w1.z*v[4*i+6] + w1.w*v[4*i+7];
        c2 += w2.x*v[4*i+8] + w2.y*v[4*i+9] + w2.z*v[4*i+10] + w2.w*v[4*i+11];
        c3 += w3.x*v[4*i+12] + w3.y*v[4*i+13] + w3.z*v[4*i+14] + w3.w*v[4*i+15];
    }
    float acc2 = (c0 + c1) + (c2 + c3);
    float nwv = sqrtf(bsum(acc2 * acc2));
    return bsum((acc2 / (nwv + EPS)) * acc2);
}

__global__ void prep_kernel(const float* __restrict__ w_ih, const float* __restrict__ w_hh,
                            const float* __restrict__ b_ih, const float* __restrict__ b_hh,
                            const float* __restrict__ u_ih, const float* __restrict__ u_hh) {
    int tid = threadIdx.x;
    if (blockIdx.x == 0) {
        float sig_ih = sigma256(w_ih, u_ih);
        float bi = b_ih[tid], bh = b_hh[tid];
        float nbi = sqrtf(bsum(bi * bi));
        float nbh = sqrtf(bsum(bh * bh));
        g_bsn[tid] = bi / (nbi + EPS) + bh / (nbh + EPS);
        if (tid == 0) g_inv_sig_ih = 1.0f / sig_ih;
    } else {
        float sig_hh = sigma256(w_hh, u_hh);
        if (tid == 0) g_inv_sig_hh = 1.0f / sig_hh;
    }
}

// ---------------- GEMM (unchanged, proven) ----------------
__global__ __launch_bounds__(256) void gemm_pre_kernel(const float* __restrict__ x,
                                                       const float* __restrict__ w,
                                                       float* __restrict__ out) {
    __shared__ __align__(16) u64 xs_d[64][32];
    __shared__ __align__(16) float ws[32][256];
    int tid = threadIdx.x;
    int row0 = blockIdx.x * 64;
    int tx = tid & 15, ty = tid >> 4;

    u64 acc[4][8];
    #pragma unroll
    for (int r = 0; r < 4; r++)
        #pragma unroll
        for (int p = 0; p < 8; p++) acc[r][p] = 0ull;

    for (int k0 = 0; k0 < 256; k0 += 32) {
        __syncthreads();
        #pragma unroll
        for (int i = 0; i < 2; i++) {
            int idx = tid + i * 256;
            int r = idx >> 3, q = idx & 7;
            float4 t4 = *(const float4*)(x + (size_t)(row0 + r) * 256 + k0 + q * 4);
            ulonglong2 p0; p0.x = pk2(t4.x, t4.x); p0.y = pk2(t4.y, t4.y);
            ulonglong2 p1; p1.x = pk2(t4.z, t4.z); p1.y = pk2(t4.w, t4.w);
            *(ulonglong2*)&xs_d[r][q * 4 + 0] = p0;
            *(ulonglong2*)&xs_d[r][q * 4 + 2] = p1;
        }
        {
            const float4* wr = (const float4*)(w + (size_t)tid * 256 + k0);
            #pragma unroll
            for (int q = 0; q < 8; q++) {
                float4 t4 = wr[q];
                ws[q * 4 + 0][tid] = t4.x;
                ws[q * 4 + 1][tid] = t4.y;
                ws[q * 4 + 2][tid] = t4.z;
                ws[q * 4 + 3][tid] = t4.w;
            }
        }
        __syncthreads();
        #pragma unroll
        for (int kk = 0; kk < 32; kk += 2) {
            ulonglong2 a01[4];
            #pragma unroll
            for (int r = 0; r < 4; r++)
                a01[r] = *(const ulonglong2*)&xs_d[ty * 4 + r][kk];
            {
                u64 bv[8];
                #pragma unroll
                for (int c = 0; c < 4; c++) {
                    ulonglong2 b2 = *(const ulonglong2*)&ws[kk][tx * 4 + c * 64];
                    bv[c*2] = b2.x; bv[c*2+1] = b2.y;
                }
                #pragma unroll
                for (int r = 0; r < 4; r++)
                    #pragma unroll
                    for (int p = 0; p < 8; p++) ffma2(acc[r][p], a01[r].x, bv[p]);
            }
            {
                u64 bv[8];
                #pragma unroll
                for (int c = 0; c < 4; c++) {
                    ulonglong2 b2 = *(const ulonglong2*)&ws[kk + 1][tx * 4 + c * 64];
                    bv[c*2] = b2.x; bv[c*2+1] = b2.y;
                }
                #pragma unroll
                for (int r = 0; r < 4; r++)
                    #pragma unroll
                    for (int p = 0; p < 8; p++) ffma2(acc[r][p], a01[r].y, bv[p]);
            }
        }
    }

    float inv = g_inv_sig_ih;
    #pragma unroll
    for (int r = 0; r < 4; r++) {
        size_t row = row0 + ty * 4 + r;
        #pragma unroll
        for (int c = 0; c < 4; c++) {
            int col = tx * 4 + c * 64;
            float4 b4 = *(const float4*)&g_bsn[col];
            float2 lo = upk2(acc[r][c*2]), hi = upk2(acc[r][c*2+1]);
            float4 o;
            o.x = lo.x * inv + b4.x;
            o.y = lo.y * inv + b4.y;
            o.z = hi.x * inv + b4.z;
            o.w = hi.y * inv + b4.w;
            *(float4*)(out + row * 256 + col) = o;
        }
    }
}

// ---------------- rnn: 4-CTA cluster, 2 batches ping-ponged ----------------
// CTA r owns k-slice AND h-rows [64r,+64) for BOTH batches; W regs shared (32 u64).
// Per step: dot_b0 -> send_b0 -> dot_b1 -> send_b1 -> wait_b0 (transit covered by
// dot_b1) -> finalize_b0 -> wait_b1 -> finalize_b1 -> bar. Transport = R13 verbatim
// (192 b32 st.async per batch-step to one owner mbarrier, expect_tx 768).
__global__ __launch_bounds__(256, 1) __cluster_dims__(4, 1, 1)
void rnn_kernel(const float* __restrict__ w_hh, const float* __restrict__ state,
                float* __restrict__ out) {
    __shared__ __align__(16) float hloc[2][2][64];   // [batch][parity][row]
    __shared__ __align__(16) float Q[2][2][4][64];   // [batch][parity][sender][row]
    __shared__ __align__(8) u64 mbar[4];             // [batch*2+parity]

    int tid = threadIdx.x;
    int c = blockIdx.x >> 2;                         // cluster -> batches 2c, 2c+1
    int rank = (int)ctarank();
    int owner = tid >> 6;
    int rl = tid & 63;
    bool mine = (owner == rank);                     // warp-uniform

    u64 wreg[32];
    {
        const float* wrow = w_hh + (size_t)tid * 256 + rank * 64;
        #pragma unroll
        for (int i = 0; i < 16; i++) {
            ulonglong2 v = *(const ulonglong2*)(wrow + 4 * i);
            wreg[2*i] = v.x; wreg[2*i+1] = v.y;
        }
    }
    float inv = g_inv_sig_hh;

    uint32_t mb[4];
    #pragma unroll
    for (int i = 0; i < 4; i++) mb[i] = smem_u32(&mbar[i]);
    uint32_t qb = smem_u32(&Q[0][0][0][0]);
    if (tid == 0) {
        #pragma unroll
        for (int i = 0; i < 4; i++) mbar_init(mb[i], 1);
    }
    if (mine) {
        hloc[0][0][rl] = state[(2*c + 0) * 256 + tid];
        hloc[1][0][rl] = state[(2*c + 1) * 256 + tid];
    }
    __syncthreads();
    cluster_sync();

    uint32_t own_q = mapa_u32(qb, (uint32_t)owner);
    uint32_t own_mb[4];
    #pragma unroll
    for (int i = 0; i < 4; i++) own_mb[i] = mapa_u32(mb[i], (uint32_t)owner);

    const size_t ts = (size_t)BB * HH;
    const float* o0 = out + (size_t)(2*c + 0) * 256 + tid;   // mine threads
    const float* o1 = out + (size_t)(2*c + 1) * 256 + tid;
    float p0c = 0.f, p0n = 0.f, p1c = 0.f, p1n = 0.f;
    if (mine) {
        p0c = __ldg(o0); p0n = __ldg(o0 + ts);
        p1c = __ldg(o1); p1n = __ldg(o1 + ts);
    }

    int s1 = (rank + 1) & 3, s2 = (rank + 2) & 3, s3 = (rank + 3) & 3;

    for (int t = 0; t < TT; t++) {
        int cur = t & 1;
        if (tid == 0) {
            mbar_arrive_expect_tx(mb[cur], 768);
            mbar_arrive_expect_tx(mb[2 + cur], 768);
        }

        // ---- batch 0 dot (64 local h, 32 FFMA2), senders ship immediately ----
        const float* h0 = hloc[0][cur];
        u64 a0 = 0ull, a1 = 0ull, a2 = 0ull, a3 = 0ull;
        #pragma unroll
        for (int i = 0; i < 8; i++) {
            ulonglong2 x0 = *(const ulonglong2*)(h0 + 8 * i);
            ulonglong2 x1 = *(const ulonglong2*)(h0 + 8 * i + 4);
            ffma2(a0, wreg[4*i+0], x0.x);
            ffma2(a1, wreg[4*i+1], x0.y);
            ffma2(a2, wreg[4*i+2], x1.x);
            ffma2(a3, wreg[4*i+3], x1.y);
        }
        float2 f0 = upk2(a0), f1 = upk2(a1), f2 = upk2(a2), f3 = upk2(a3);
        float pA = ((f0.x + f0.y) + (f1.x + f1.y)) + ((f2.x + f2.y) + (f3.x + f3.y));
        if (!mine)
            st_async_b32(own_q + (uint32_t)((((0*2 + cur) * 4 + rank) * 64 + rl) * 4),
                         __float_as_uint(pA), own_mb[cur]);

        // ---- batch 1 dot (covers batch 0's transit) ----
        const float* h1 = hloc[1][cur];
        u64 b0 = 0ull, b1 = 0ull, b2 = 0ull, b3 = 0ull;
        #pragma unroll
        for (int i = 0; i < 8; i++) {
            ulonglong2 x0 = *(const ulonglong2*)(h1 + 8 * i);
            ulonglong2 x1 = *(const ulonglong2*)(h1 + 8 * i + 4);
            ffma2(b0, wreg[4*i+0], x0.x);
            ffma2(b1, wreg[4*i+1], x0.y);
            ffma2(b2, wreg[4*i+2], x1.x);
            ffma2(b3, wreg[4*i+3], x1.y);
        }
        float2 g0 = upk2(b0), g1 = upk2(b1), g2 = upk2(b2), g3 = upk2(b3);
        float pB = ((g0.x + g0.y) + (g1.x + g1.y)) + ((g2.x + g2.y) + (g3.x + g3.y));
        if (!mine)
            st_async_b32(own_q + (uint32_t)((((1*2 + cur) * 4 + rank) * 64 + rl) * 4),
                         __float_as_uint(pB), own_mb[2 + cur]);

        if (mine) {
            float p0n2 = (t + 2 < TT) ? __ldg(o0 + (size_t)(t + 2) * ts) : 0.f;
            float p1n2 = (t + 2 < TT) ? __ldg(o1 + (size_t)(t + 2) * ts) : 0.f;
            uint32_t par = (uint32_t)((t >> 1) & 1);

            waitpar(mb[cur], par);
            float sA = pA + Q[0][cur][s1][rl] + Q[0][cur][s2][rl] + Q[0][cur][s3][rl];
            float hn0 = tanh_fast(fmaf(inv, sA, p0c));
            out[(size_t)t * ts + (size_t)(2*c + 0) * 256 + tid] = hn0;
            hloc[0][cur ^ 1][rl] = hn0;

            waitpar(mb[2 + cur], par);
            float sB = pB + Q[1][cur][s1][rl] + Q[1][cur][s2][rl] + Q[1][cur][s3][rl];
            float hn1 = tanh_fast(fmaf(inv, sB, p1c));
            out[(size_t)t * ts + (size_t)(2*c + 1) * 256 + tid] = hn1;
            hloc[1][cur ^ 1][rl] = hn1;

            if (t == TT - 1) {
                out[(size_t)TT * ts + (size_t)(2*c + 0) * 256 + tid] = hn0;
                out[(size_t)TT * ts + (size_t)(2*c + 1) * 256 + tid] = hn1;
            }
            p0c = p0n; p0n = p0n2;
            p1c = p1n; p1n = p1n2;
        }
        __syncthreads();
    }
    cluster_sync();
}

extern "C" void kernel_launch(void* const* d_in, const int* in_sizes, int n_in,
                              void* d_out, int out_size) {
    const float* x     = (const float*)d_in[0];
    const float* state = (const float*)d_in[1];
    const float* w_ih  = (const float*)d_in[2];
    const float* w_hh  = (const float*)d_in[3];
    const float* b_ih  = (const float*)d_in[4];
    const float* b_hh  = (const float*)d_in[5];
    const float* u_ih  = (const float*)d_in[6];
    const float* u_hh  = (const float*)d_in[7];
    float* out = (float*)d_out;

    prep_kernel<<<2, 256>>>(w_ih, w_hh, b_ih, b_hh, u_ih, u_hh);
    gemm_pre_kernel<<<(TT * BB) / 64, 256>>>(x, w_ih, out);
    rnn_kernel<<<(BB / 2) * 4, 256>>>(w_hh, state, out);   // 16 clusters x 4 CTAs
}

// round 16
// speedup vs baseline: 1.8651x; 1.8651x over previous
#include <cuda_runtime.h>
#include <cuda_bf16.h>
#include <cstdint>

#define TT 4096
#define BB 32
#define HH 256
#define EPS 1e-12f

typedef unsigned long long u64;

// ---------------- device globals ----------------
__device__ float g_bsn[HH];
__device__ float g_inv_sig_ih;
__device__ float g_inv_sig_hh;

// ---------------- PTX helpers ----------------
__device__ __forceinline__ void ffma2(u64& d, u64 a, u64 b) {
    asm("fma.rn.f32x2 %0, %1, %2, %0;" : "+l"(d) : "l"(a), "l"(b));
}
__device__ __forceinline__ u64 pk2(float x, float y) {
    u64 r; asm("mov.b64 %0, {%1, %2};" : "=l"(r) : "f"(x), "f"(y));
    return r;
}
__device__ __forceinline__ float2 upk2(u64 v) {
    float lo, hi; asm("mov.b64 {%0, %1}, %2;" : "=f"(lo), "=f"(hi) : "l"(v));
    return make_float2(lo, hi);
}
__device__ __forceinline__ uint32_t smem_u32(const void* p) {
    uint32_t a;
    asm("{ .reg .u64 t; cvta.to.shared.u64 t, %1; cvt.u32.u64 %0, t; }" : "=r"(a) : "l"(p));
    return a;
}
__device__ __forceinline__ uint32_t mapa_u32(uint32_t a, uint32_t r) {
    uint32_t d; asm("mapa.shared::cluster.u32 %0, %1, %2;" : "=r"(d) : "r"(a), "r"(r));
    return d;
}
__device__ __forceinline__ uint32_t ctarank() {
    uint32_t r; asm("mov.u32 %0, %%cluster_ctarank;" : "=r"(r));
    return r;
}
__device__ __forceinline__ void mbar_init(uint32_t mb, uint32_t cnt) {
    asm volatile("mbarrier.init.shared.b64 [%0], %1;" :: "r"(mb), "r"(cnt) : "memory");
}
__device__ __forceinline__ void mbar_arrive_expect_tx(uint32_t mb, uint32_t tx) {
    asm volatile("mbarrier.arrive.expect_tx.shared.b64 _, [%0], %1;" :: "r"(mb), "r"(tx) : "memory");
}
__device__ __forceinline__ void st_async_b32(uint32_t raddr, uint32_t v, uint32_t rmbar) {
    asm volatile("st.async.shared::cluster.mbarrier::complete_tx::bytes.b32 [%0], %1, [%2];"
                 :: "r"(raddr), "r"(v), "r"(rmbar) : "memory");
}
// CTA-scope acquire: data visibility of complete_tx ops (st.async/TMA) is
// guaranteed by barrier phase completion; cluster-scope acquire would emit
// CCTL.IVALL (L1 flush) every poll iteration.
__device__ __forceinline__ void waitpar(uint32_t mb, uint32_t par) {
    uint32_t done;
    do {
        asm volatile(
            "{\n\t"
            ".reg .pred p;\n\t"
            "mbarrier.try_wait.parity.acquire.cta.shared::cta.b64 p, [%1], %2, 0x989680;\n\t"
            "selp.b32 %0, 1, 0, p;\n\t"
            "}" : "=r"(done) : "r"(mb), "r"(par) : "memory");
    } while (!done);
}
__device__ __forceinline__ float tanh_fast(float x) {
    float r; asm("tanh.approx.f32 %0, %1;" : "=f"(r) : "f"(x));
    return r;
}
__device__ __forceinline__ void cluster_sync() {
    asm volatile("barrier.cluster.arrive.aligned;" ::: "memory");
    asm volatile("barrier.cluster.wait.aligned;" ::: "memory");
}

// ---------------- prep: spectral norms + bias (2 blocks, one sigma each) -----------
__device__ float bsum(float v) {
    __shared__ float sred[8];
    int lane = threadIdx.x & 31, w = threadIdx.x >> 5;
    #pragma unroll
    for (int o = 16; o; o >>= 1) v += __shfl_xor_sync(0xffffffffu, v, o);
    if (lane == 0) sred[w] = v;
    __syncthreads();
    float r = sred[0];
    #pragma unroll
    for (int i = 1; i < 8; i++) r += sred[i];
    __syncthreads();
    return r;
}

__device__ float sigma256(const float* __restrict__ w, const float* __restrict__ u0) {
    __shared__ float u[256], v[256];
    int tid = threadIdx.x;
    float u0t = u0[tid];
    float nu = sqrtf(bsum(u0t * u0t));
    u[tid] = u0t / (nu + EPS);
    __syncthreads();
    // t = W^T u : 4 independent accumulator chains
    float a0 = 0.f, a1 = 0.f, a2 = 0.f, a3 = 0.f;
    #pragma unroll 4
    for (int j = 0; j < 256; j += 4) {
        a0 += w[(j + 0) * 256 + tid] * u[j + 0];
        a1 += w[(j + 1) * 256 + tid] * u[j + 1];
        a2 += w[(j + 2) * 256 + tid] * u[j + 2];
        a3 += w[(j + 3) * 256 + tid] * u[j + 3];
    }
    float acc = (a0 + a1) + (a2 + a3);
    float nv = sqrtf(bsum(acc * acc));
    v[tid] = acc / (nv + EPS);
    __syncthreads();
    // wv = W v ; sigma = l2norm(wv) . wv   (4 chains, float4 loads)
    float c0 = 0.f, c1 = 0.f, c2 = 0.f, c3 = 0.f;
    const float4* wr = (const float4*)(w + (size_t)tid * 256);
    #pragma unroll 4
    for (int i = 0; i < 64; i += 4) {
        float4 w0 = wr[i], w1 = wr[i + 1], w2 = wr[i + 2], w3 = wr[i + 3];
        c0 += w0.x * v[4*i+0] + w0.y * v[4*i+1] + w0.z * v[4*i+2] + w0.w * v[4*i+3];
        c1 += w1.x * v[4*i+4] + w1.y * v[4*i+5] + w1.z * v[4*i+6] + w1.w * v[4*i+7];
        c2 += w2.x * v[4*i+8] + w2.y * v[4*i+9] + w2.z * v[4*i+10] + w2.w * v[4*i+11];
        c3 += w3.x * v[4*i+12] + w3.y * v[4*i+13] + w3.z * v[4*i+14] + w3.w * v[4*i+15];
    }
    float acc2 = (c0 + c1) + (c2 + c3);
    float nwv = sqrtf(bsum(acc2 * acc2));
    float sig = bsum((acc2 / (nwv + EPS)) * acc2);
    return sig;
}

__global__ void prep_kernel(const float* __restrict__ w_ih, const float* __restrict__ w_hh,
                            const float* __restrict__ b_ih, const float* __restrict__ b_hh,
                            const float* __restrict__ u_ih, const float* __restrict__ u_hh) {
    int tid = threadIdx.x;
    if (blockIdx.x == 0) {
        float sig_ih = sigma256(w_ih, u_ih);
        float bi = b_ih[tid], bh = b_hh[tid];
        float nbi = sqrtf(bsum(bi * bi));
        float nbh = sqrtf(bsum(bh * bh));
        g_bsn[tid] = bi / (nbi + EPS) + bh / (nbh + EPS);
        if (tid == 0) g_inv_sig_ih = 1.0f / sig_ih;
    } else {
        float sig_hh = sigma256(w_hh, u_hh);
        if (tid == 0) g_inv_sig_hh = 1.0f / sig_hh;
    }
}

// ---------------- GEMM: pre = x @ w_ih^T * inv_sig + b_sn  -> d_out ----------------
// CTA tile 64 rows x 256 cols, KT=32. xs stored PRE-PACKED as f32x2 duplicates
// (16KB) so the mainloop is pure LDS.128 + FFMA2. ws transposed (32KB).
// Thread (tx,ty): rows ty*4..+3, cols {tx*4 + c*64}. 48KB static smem exactly.
__global__ __launch_bounds__(256) void gemm_pre_kernel(const float* __restrict__ x,
                                                       const float* __restrict__ w,
                                                       float* __restrict__ out) {
    __shared__ __align__(16) u64 xs_d[64][32];      // 16384 B
    __shared__ __align__(16) float ws[32][256];     // 32768 B
    int tid = threadIdx.x;
    int row0 = blockIdx.x * 64;

    int tx = tid & 15;
    int ty = tid >> 4;

    u64 acc[4][8];
    #pragma unroll
    for (int r = 0; r < 4; r++)
        #pragma unroll
        for (int p = 0; p < 8; p++) acc[r][p] = 0ull;

    for (int k0 = 0; k0 < 256; k0 += 32) {
        __syncthreads();
        // xs fill: 512 float4 loads, 2 per thread -> packed duplicate pairs
        #pragma unroll
        for (int i = 0; i < 2; i++) {
            int idx = tid + i * 256;
            int r = idx >> 3, q = idx & 7;
            float4 t4 = *(const float4*)(x + (size_t)(row0 + r) * 256 + k0 + q * 4);
            ulonglong2 p0; p0.x = pk2(t4.x, t4.x); p0.y = pk2(t4.y, t4.y);
            ulonglong2 p1; p1.x = pk2(t4.z, t4.z); p1.y = pk2(t4.w, t4.w);
            *(ulonglong2*)&xs_d[r][q * 4 + 0] = p0;
            *(ulonglong2*)&xs_d[r][q * 4 + 2] = p1;
        }
        // ws fill transposed: thread owns W row j=tid (lane-distinct -> conflict-free)
        {
            const float4* wr = (const float4*)(w + (size_t)tid * 256 + k0);
            #pragma unroll
            for (int q = 0; q < 8; q++) {
                float4 t4 = wr[q];
                ws[q * 4 + 0][tid] = t4.x;
                ws[q * 4 + 1][tid] = t4.y;
                ws[q * 4 + 2][tid] = t4.z;
                ws[q * 4 + 3][tid] = t4.w;
            }
        }
        __syncthreads();
        #pragma unroll
        for (int kk = 0; kk < 32; kk += 2) {
            ulonglong2 a01[4];
            #pragma unroll
            for (int r = 0; r < 4; r++)
                a01[r] = *(const ulonglong2*)&xs_d[ty * 4 + r][kk];
            // sub-k 0
            {
                u64 bv[8];
                #pragma unroll
                for (int c = 0; c < 4; c++) {
                    ulonglong2 b2 = *(const ulonglong2*)&ws[kk][tx * 4 + c * 64];
                    bv[c * 2 + 0] = b2.x; bv[c * 2 + 1] = b2.y;
                }
                #pragma unroll
                for (int r = 0; r < 4; r++)
                    #pragma unroll
                    for (int p = 0; p < 8; p++) ffma2(acc[r][p], a01[r].x, bv[p]);
            }
            // sub-k 1
            {
                u64 bv[8];
                #pragma unroll
                for (int c = 0; c < 4; c++) {
                    ulonglong2 b2 = *(const ulonglong2*)&ws[kk + 1][tx * 4 + c * 64];
                    bv[c * 2 + 0] = b2.x; bv[c * 2 + 1] = b2.y;
                }
                #pragma unroll
                for (int r = 0; r < 4; r++)
                    #pragma unroll
                    for (int p = 0; p < 8; p++) ffma2(acc[r][p], a01[r].y, bv[p]);
            }
        }
    }

    float inv = g_inv_sig_ih;
    #pragma unroll
    for (int r = 0; r < 4; r++) {
        size_t row = row0 + ty * 4 + r;
        #pragma unroll
        for (int c = 0; c < 4; c++) {
            int col = tx * 4 + c * 64;
            float4 b4 = *(const float4*)&g_bsn[col];
            float2 lo = upk2(acc[r][c * 2 + 0]);
            float2 hi = upk2(acc[r][c * 2 + 1]);
            float4 o;
            o.x = lo.x * inv + b4.x;
            o.y = lo.y * inv + b4.y;
            o.z = hi.x * inv + b4.z;
            o.w = hi.y * inv + b4.w;
            *(float4*)(out + row * 256 + col) = o;
        }
    }
}

// ---------------- recurrence: 2-CTA cluster per batch, column-split W ----------------
__global__ __launch_bounds__(256, 1) __cluster_dims__(2, 1, 1)
void rnn_kernel(const float* __restrict__ w_hh, const float* __restrict__ state,
                float* __restrict__ out) {
    __shared__ __align__(16) float hbuf[2][128];
    __shared__ __align__(16) float Qbuf[2][128];   // peer partials land here
    __shared__ __align__(8) u64 mbar[2];

    int tid = threadIdx.x;
    int b = blockIdx.x >> 1;
    uint32_t rank = ctarank();
    bool ownrow = tid < 128;           // warps 0-3: own rows; warps 4-7: peer rows
    int rloc = tid & 127;
    int jj = ownrow ? ((int)rank * 128 + rloc) : (((int)rank ^ 1) * 128 + rloc);

    // W slice: row jj, cols [rank*128, +128) as 64 f32x2 pairs
    u64 wreg[64];
    {
        const float* wrow = w_hh + (size_t)jj * 256 + rank * 128;
        #pragma unroll
        for (int i = 0; i < 32; i++) {
            ulonglong2 v = *(const ulonglong2*)(wrow + 4 * i);
            wreg[2 * i + 0] = v.x;
            wreg[2 * i + 1] = v.y;
        }
    }
    float inv = g_inv_sig_hh;

    uint32_t mb0 = smem_u32(&mbar[0]);
    uint32_t mb1 = smem_u32(&mbar[1]);
    uint32_t q0  = smem_u32(&Qbuf[0][0]);
    if (tid == 0) { mbar_init(mb0, 1); mbar_init(mb1, 1); }
    if (ownrow) hbuf[0][rloc] = state[b * 256 + rank * 128 + rloc];
    __syncthreads();
    cluster_sync();   // peer mbarriers/smem visible before any st.async

    uint32_t peer = rank ^ 1;
    uint32_t peer_q   = mapa_u32(q0, peer);
    uint32_t peer_mb0 = mapa_u32(mb0, peer);
    uint32_t peer_mb1 = mapa_u32(mb1, peer);

    const size_t tstride = (size_t)BB * HH;
    float* outp = out + (size_t)b * 256 + rank * 128 + rloc;   // ownrow threads only
    float pre_cur = ownrow ? __ldg(outp) : 0.f;
    float pre_n1  = ownrow ? __ldg(outp + tstride) : 0.f;

    for (int t = 0; t < TT; t++) {
        int cur = t & 1;
        uint32_t mb_cur = cur ? mb1 : mb0;
        if (tid == 0) mbar_arrive_expect_tx(mb_cur, 512);   // arm: 128 x 4B incoming

        // 2-deep software pipeline on pre (covers DRAM latency without L1)
        float pre_n2 = (ownrow && t + 2 < TT) ? __ldg(outp + (size_t)(t + 2) * tstride) : 0.f;

        // partial dot over locally-produced h half (broadcast smem reads, FFMA2)
        const float* hc = hbuf[cur];
        u64 a0 = 0ull, a1 = 0ull, a2 = 0ull, a3 = 0ull;
        #pragma unroll
        for (int i = 0; i < 16; i++) {
            ulonglong2 h0 = *(const ulonglong2*)(hc + 8 * i);
            ulonglong2 h1 = *(const ulonglong2*)(hc + 8 * i + 4);
            ffma2(a0, wreg[4 * i + 0], h0.x);
            ffma2(a1, wreg[4 * i + 1], h0.y);
            ffma2(a2, wreg[4 * i + 2], h1.x);
            ffma2(a3, wreg[4 * i + 3], h1.y);
        }
        float2 f0 = upk2(a0), f1 = upk2(a1), f2 = upk2(a2), f3 = upk2(a3);
        float partial = ((f0.x + f0.y) + (f1.x + f1.y)) + ((f2.x + f2.y) + (f3.x + f3.y));

        if (!ownrow) {
            // ship peer-row partial immediately (warps 4-7 finish first by hi-wid priority)
            st_async_b32(peer_q + (uint32_t)((cur * 128 + rloc) * 4),
                         __float_as_uint(partial), cur ? peer_mb1 : peer_mb0);
        } else {
            waitpar(mb_cur, (uint32_t)((t >> 1) & 1));
            float s = partial + Qbuf[cur][rloc];
            float hn = tanh_fast(fmaf(inv, s, pre_cur));
            outp[(size_t)t * tstride] = hn;
            hbuf[cur ^ 1][rloc] = hn;
            if (t == TT - 1)
                out[(size_t)TT * tstride + (size_t)b * 256 + rank * 128 + rloc] = hn;
        }
        __syncthreads();   // hbuf[nxt] visible to all warps
        pre_cur = pre_n1;
        pre_n1 = pre_n2;
    }
    cluster_sync();  // keep peer smem alive for in-flight remote ops
}

// ---------------- launch ----------------
extern "C" void kernel_launch(void* const* d_in, const int* in_sizes, int n_in,
                              void* d_out, int out_size) {
    const float* x     = (const float*)d_in[0];
    const float* state = (const float*)d_in[1];
    const float* w_ih  = (const float*)d_in[2];
    const float* w_hh  = (const float*)d_in[3];
    const float* b_ih  = (const float*)d_in[4];
    const float* b_hh  = (const float*)d_in[5];
    const float* u_ih  = (const float*)d_in[6];
    const float* u_hh  = (const float*)d_in[7];
    float* out = (float*)d_out;

    prep_kernel<<<2, 256>>>(w_ih, w_hh, b_ih, b_hh, u_ih, u_hh);
    gemm_pre_kernel<<<(TT * BB) / 64, 256>>>(x, w_ih, out);
    rnn_kernel<<<2 * BB, 256>>>(w_hh, state, out);
}

// round 17
// speedup vs baseline: 1.9007x; 1.0191x over previous
#include <cuda_runtime.h>
#include <cstdint>

#define TT 4096
#define BB 32
#define HH 256
#define EPS 1e-12f

typedef unsigned long long u64;

// ---------------- PTX helpers ----------------
__device__ __forceinline__ void ffma2(u64& d, u64 a, u64 b) {
    asm("fma.rn.f32x2 %0, %1, %2, %0;" : "+l"(d) : "l"(a), "l"(b));
}
__device__ __forceinline__ u64 pk2(float x, float y) {
    u64 r; asm("mov.b64 %0, {%1, %2};" : "=l"(r) : "f"(x), "f"(y));
    return r;
}
__device__ __forceinline__ float2 upk2(u64 v) {
    float lo, hi; asm("mov.b64 {%0, %1}, %2;" : "=f"(lo), "=f"(hi) : "l"(v));
    return make_float2(lo, hi);
}
__device__ __forceinline__ uint32_t smem_u32(const void* p) {
    uint32_t a;
    asm("{ .reg .u64 t; cvta.to.shared.u64 t, %1; cvt.u32.u64 %0, t; }" : "=r"(a) : "l"(p));
    return a;
}
__device__ __forceinline__ uint32_t mapa_u32(uint32_t a, uint32_t r) {
    uint32_t d; asm("mapa.shared::cluster.u32 %0, %1, %2;" : "=r"(d) : "r"(a), "r"(r));
    return d;
}
__device__ __forceinline__ uint32_t ctarank() {
    uint32_t r; asm("mov.u32 %0, %%cluster_ctarank;" : "=r"(r));
    return r;
}
__device__ __forceinline__ void mbar_init(uint32_t mb, uint32_t cnt) {
    asm volatile("mbarrier.init.shared.b64 [%0], %1;" :: "r"(mb), "r"(cnt) : "memory");
}
__device__ __forceinline__ void mbar_arrive_expect_tx(uint32_t mb, uint32_t tx) {
    asm volatile("mbarrier.arrive.expect_tx.shared.b64 _, [%0], %1;" :: "r"(mb), "r"(tx) : "memory");
}
__device__ __forceinline__ void st_async_b32(uint32_t raddr, uint32_t v, uint32_t rmbar) {
    asm volatile("st.async.shared::cluster.mbarrier::complete_tx::bytes.b32 [%0], %1, [%2];"
                 :: "r"(raddr), "r"(v), "r"(rmbar) : "memory");
}
// CTA-scope acquire: data visibility of complete_tx ops is guaranteed by barrier
// phase completion; cluster-scope acquire would emit CCTL.IVALL per poll.
__device__ __forceinline__ void waitpar(uint32_t mb, uint32_t par) {
    uint32_t done;
    do {
        asm volatile(
            "{\n\t"
            ".reg .pred p;\n\t"
            "mbarrier.try_wait.parity.acquire.cta.shared::cta.b64 p, [%1], %2, 0x989680;\n\t"
            "selp.b32 %0, 1, 0, p;\n\t"
            "}" : "=r"(done) : "r"(mb), "r"(par) : "memory");
    } while (!done);
}
__device__ __forceinline__ float tanh_fast(float x) {
    float r; asm("tanh.approx.f32 %0, %1;" : "=f"(r) : "f"(x));
    return r;
}
__device__ __forceinline__ void cluster_sync() {
    asm volatile("barrier.cluster.arrive.aligned;" ::: "memory");
    asm volatile("barrier.cluster.wait.aligned;" ::: "memory");
}

// ---------------- sigma helpers (now run inside the rnn kernel) ----------------
__device__ float bsum(float v) {
    __shared__ float sred[8];
    int lane = threadIdx.x & 31, w = threadIdx.x >> 5;
    #pragma unroll
    for (int o = 16; o; o >>= 1) v += __shfl_xor_sync(0xffffffffu, v, o);
    if (lane == 0) sred[w] = v;
    __syncthreads();
    float r = sred[0];
    #pragma unroll
    for (int i = 1; i < 8; i++) r += sred[i];
    __syncthreads();
    return r;
}

__device__ float sigma256(const float* __restrict__ w, const float* __restrict__ u0) {
    __shared__ float u[256], v[256];
    int tid = threadIdx.x;
    float u0t = u0[tid];
    float nu = sqrtf(bsum(u0t * u0t));
    u[tid] = u0t / (nu + EPS);
    __syncthreads();
    // t = W^T u : 4 independent accumulator chains
    float a0 = 0.f, a1 = 0.f, a2 = 0.f, a3 = 0.f;
    #pragma unroll 4
    for (int j = 0; j < 256; j += 4) {
        a0 += w[(j + 0) * 256 + tid] * u[j + 0];
        a1 += w[(j + 1) * 256 + tid] * u[j + 1];
        a2 += w[(j + 2) * 256 + tid] * u[j + 2];
        a3 += w[(j + 3) * 256 + tid] * u[j + 3];
    }
    float acc = (a0 + a1) + (a2 + a3);
    float nv = sqrtf(bsum(acc * acc));
    v[tid] = acc / (nv + EPS);
    __syncthreads();
    // wv = W v ; sigma = l2norm(wv) . wv
    float c0 = 0.f, c1 = 0.f, c2 = 0.f, c3 = 0.f;
    const float4* wr = (const float4*)(w + (size_t)tid * 256);
    #pragma unroll 4
    for (int i = 0; i < 64; i += 4) {
        float4 w0 = wr[i], w1 = wr[i + 1], w2 = wr[i + 2], w3 = wr[i + 3];
        c0 += w0.x * v[4*i+0] + w0.y * v[4*i+1] + w0.z * v[4*i+2] + w0.w * v[4*i+3];
        c1 += w1.x * v[4*i+4] + w1.y * v[4*i+5] + w1.z * v[4*i+6] + w1.w * v[4*i+7];
        c2 += w2.x * v[4*i+8] + w2.y * v[4*i+9] + w2.z * v[4*i+10] + w2.w * v[4*i+11];
        c3 += w3.x * v[4*i+12] + w3.y * v[4*i+13] + w3.z * v[4*i+14] + w3.w * v[4*i+15];
    }
    float acc2 = (c0 + c1) + (c2 + c3);
    float nwv = sqrtf(bsum(acc2 * acc2));
    float sig = bsum((acc2 / (nwv + EPS)) * acc2);
    __syncthreads();
    return sig;
}

// ---------------- GEMM: raw = x @ w_ih^T  -> d_out (scale+bias applied in rnn) -----
// CTA tile 64 rows x 256 cols, KT=32. xs pre-packed as f32x2 duplicates (16KB),
// ws transposed (32KB). No prep dependency -> launches immediately.
__global__ __launch_bounds__(256) void gemm_pre_kernel(const float* __restrict__ x,
                                                       const float* __restrict__ w,
                                                       float* __restrict__ out) {
    __shared__ __align__(16) u64 xs_d[64][32];      // 16384 B
    __shared__ __align__(16) float ws[32][256];     // 32768 B
    int tid = threadIdx.x;
    int row0 = blockIdx.x * 64;

    int tx = tid & 15;
    int ty = tid >> 4;

    u64 acc[4][8];
    #pragma unroll
    for (int r = 0; r < 4; r++)
        #pragma unroll
        for (int p = 0; p < 8; p++) acc[r][p] = 0ull;

    for (int k0 = 0; k0 < 256; k0 += 32) {
        __syncthreads();
        #pragma unroll
        for (int i = 0; i < 2; i++) {
            int idx = tid + i * 256;
            int r = idx >> 3, q = idx & 7;
            float4 t4 = *(const float4*)(x + (size_t)(row0 + r) * 256 + k0 + q * 4);
            ulonglong2 p0; p0.x = pk2(t4.x, t4.x); p0.y = pk2(t4.y, t4.y);
            ulonglong2 p1; p1.x = pk2(t4.z, t4.z); p1.y = pk2(t4.w, t4.w);
            *(ulonglong2*)&xs_d[r][q * 4 + 0] = p0;
            *(ulonglong2*)&xs_d[r][q * 4 + 2] = p1;
        }
        {
            const float4* wr = (const float4*)(w + (size_t)tid * 256 + k0);
            #pragma unroll
            for (int q = 0; q < 8; q++) {
                float4 t4 = wr[q];
                ws[q * 4 + 0][tid] = t4.x;
                ws[q * 4 + 1][tid] = t4.y;
                ws[q * 4 + 2][tid] = t4.z;
                ws[q * 4 + 3][tid] = t4.w;
            }
        }
        __syncthreads();
        #pragma unroll
        for (int kk = 0; kk < 32; kk += 2) {
            ulonglong2 a01[4];
            #pragma unroll
            for (int r = 0; r < 4; r++)
                a01[r] = *(const ulonglong2*)&xs_d[ty * 4 + r][kk];
            {
                u64 bv[8];
                #pragma unroll
                for (int c = 0; c < 4; c++) {
                    ulonglong2 b2 = *(const ulonglong2*)&ws[kk][tx * 4 + c * 64];
                    bv[c * 2 + 0] = b2.x; bv[c * 2 + 1] = b2.y;
                }
                #pragma unroll
                for (int r = 0; r < 4; r++)
                    #pragma unroll
                    for (int p = 0; p < 8; p++) ffma2(acc[r][p], a01[r].x, bv[p]);
            }
            {
                u64 bv[8];
                #pragma unroll
                for (int c = 0; c < 4; c++) {
                    ulonglong2 b2 = *(const ulonglong2*)&ws[kk + 1][tx * 4 + c * 64];
                    bv[c * 2 + 0] = b2.x; bv[c * 2 + 1] = b2.y;
                }
                #pragma unroll
                for (int r = 0; r < 4; r++)
                    #pragma unroll
                    for (int p = 0; p < 8; p++) ffma2(acc[r][p], a01[r].y, bv[p]);
            }
        }
    }

    #pragma unroll
    for (int r = 0; r < 4; r++) {
        size_t row = row0 + ty * 4 + r;
        #pragma unroll
        for (int c = 0; c < 4; c++) {
            int col = tx * 4 + c * 64;
            float2 lo = upk2(acc[r][c * 2 + 0]);
            float2 hi = upk2(acc[r][c * 2 + 1]);
            float4 o;
            o.x = lo.x;
            o.y = lo.y;
            o.z = hi.x;
            o.w = hi.y;
            *(float4*)(out + row * 256 + col) = o;
        }
    }
}

// ---------------- recurrence: 2-CTA cluster per batch, column-split W ----------------
// Identical transport/roles to the champion; sigma/bias now computed in-prologue
// (per-CTA redundantly), and pre is reconstructed as fmaf(raw, inv_ih, bsn) —
// the same FFMA the gemm epilogue used to perform, so results are bit-exact.
__global__ __launch_bounds__(256, 1) __cluster_dims__(2, 1, 1)
void rnn_kernel(const float* __restrict__ w_hh, const float* __restrict__ w_ih,
                const float* __restrict__ state,
                const float* __restrict__ b_ih, const float* __restrict__ b_hh,
                const float* __restrict__ u_ih, const float* __restrict__ u_hh,
                float* __restrict__ out) {
    __shared__ __align__(16) float hbuf[2][128];
    __shared__ __align__(16) float Qbuf[2][128];   // peer partials land here
    __shared__ __align__(8) u64 mbar[2];

    int tid = threadIdx.x;
    int b = blockIdx.x >> 1;
    uint32_t rank = ctarank();
    bool ownrow = tid < 128;           // warps 0-3: own rows; warps 4-7: peer rows
    int rloc = tid & 127;
    int jj = ownrow ? ((int)rank * 128 + rloc) : (((int)rank ^ 1) * 128 + rloc);

    // ---- in-kernel prep (replaces the prep launch): sigmas + per-row bias ----
    float sig_ih = sigma256(w_ih, u_ih);
    float sig_hh = sigma256(w_hh, u_hh);
    float bt = b_ih[tid], ht = b_hh[tid];
    float nbi = sqrtf(bsum(bt * bt));
    float nbh = sqrtf(bsum(ht * ht));
    float inv_ih = 1.0f / sig_ih;
    float inv    = 1.0f / sig_hh;
    float bsn_r = 0.f;
    if (ownrow) bsn_r = b_ih[jj] / (nbi + EPS) + b_hh[jj] / (nbh + EPS);

    // W slice: row jj, cols [rank*128, +128) as 64 f32x2 pairs
    u64 wreg[64];
    {
        const float* wrow = w_hh + (size_t)jj * 256 + rank * 128;
        #pragma unroll
        for (int i = 0; i < 32; i++) {
            ulonglong2 v = *(const ulonglong2*)(wrow + 4 * i);
            wreg[2 * i + 0] = v.x;
            wreg[2 * i + 1] = v.y;
        }
    }

    uint32_t mb0 = smem_u32(&mbar[0]);
    uint32_t mb1 = smem_u32(&mbar[1]);
    uint32_t q0  = smem_u32(&Qbuf[0][0]);
    if (tid == 0) { mbar_init(mb0, 1); mbar_init(mb1, 1); }
    if (ownrow) hbuf[0][rloc] = state[b * 256 + rank * 128 + rloc];
    __syncthreads();
    cluster_sync();   // peer mbarriers/smem visible before any st.async

    uint32_t peer = rank ^ 1;
    uint32_t peer_q   = mapa_u32(q0, peer);
    uint32_t peer_mb0 = mapa_u32(mb0, peer);
    uint32_t peer_mb1 = mapa_u32(mb1, peer);

    const size_t tstride = (size_t)BB * HH;
    float* outp = out + (size_t)b * 256 + rank * 128 + rloc;   // ownrow threads only
    float pre_cur = ownrow ? __ldg(outp) : 0.f;                // raw values
    float pre_n1  = ownrow ? __ldg(outp + tstride) : 0.f;

    for (int t = 0; t < TT; t++) {
        int cur = t & 1;
        uint32_t mb_cur = cur ? mb1 : mb0;
        if (tid == 0) mbar_arrive_expect_tx(mb_cur, 512);   // arm: 128 x 4B incoming

        // 2-deep software pipeline on raw pre
        float pre_n2 = (ownrow && t + 2 < TT) ? __ldg(outp + (size_t)(t + 2) * tstride) : 0.f;

        // partial dot over locally-produced h half (broadcast smem reads, FFMA2)
        const float* hc = hbuf[cur];
        u64 a0 = 0ull, a1 = 0ull, a2 = 0ull, a3 = 0ull;
        #pragma unroll
        for (int i = 0; i < 16; i++) {
            ulonglong2 h0 = *(const ulonglong2*)(hc + 8 * i);
            ulonglong2 h1 = *(const ulonglong2*)(hc + 8 * i + 4);
            ffma2(a0, wreg[4 * i + 0], h0.x);
            ffma2(a1, wreg[4 * i + 1], h0.y);
            ffma2(a2, wreg[4 * i + 2], h1.x);
            ffma2(a3, wreg[4 * i + 3], h1.y);
        }
        float2 f0 = upk2(a0), f1 = upk2(a1), f2 = upk2(a2), f3 = upk2(a3);
        float partial = ((f0.x + f0.y) + (f1.x + f1.y)) + ((f2.x + f2.y) + (f3.x + f3.y));

        if (!ownrow) {
            st_async_b32(peer_q + (uint32_t)((cur * 128 + rloc) * 4),
                         __float_as_uint(partial), cur ? peer_mb1 : peer_mb0);
        } else {
            waitpar(mb_cur, (uint32_t)((t >> 1) & 1));
            float s = partial + Qbuf[cur][rloc];
            float base = fmaf(pre_cur, inv_ih, bsn_r);     // == old gemm epilogue FFMA
            float hn = tanh_fast(fmaf(inv, s, base));
            outp[(size_t)t * tstride] = hn;
            hbuf[cur ^ 1][rloc] = hn;
            if (t == TT - 1)
                out[(size_t)TT * tstride + (size_t)b * 256 + rank * 128 + rloc] = hn;
        }
        __syncthreads();   // hbuf[nxt] visible to all warps
        pre_cur = pre_n1;
        pre_n1 = pre_n2;
    }
    cluster_sync();  // keep peer smem alive for in-flight remote ops
}

// ---------------- launch ----------------
extern "C" void kernel_launch(void* const* d_in, const int* in_sizes, int n_in,
                              void* d_out, int out_size) {
    const float* x     = (const float*)d_in[0];
    const float* state = (const float*)d_in[1];
    const float* w_ih  = (const float*)d_in[2];
    const float* w_hh  = (const float*)d_in[3];
    const float* b_ih  = (const float*)d_in[4];
    const float* b_hh  = (const float*)d_in[5];
    const float* u_ih  = (const float*)d_in[6];
    const float* u_hh  = (const float*)d_in[7];
    float* out = (float*)d_out;

    gemm_pre_kernel<<<(TT * BB) / 64, 256>>>(x, w_ih, out);
    rnn_kernel<<<2 * BB, 256>>>(w_hh, w_ih, state, b_ih, b_hh, u_ih, u_hh, out);
}